// round 1
// baseline (speedup 1.0000x reference)
#include <cuda_runtime.h>

// Problem constants (fixed shapes for this problem instance)
#define NROWS   4096      // b*n*h = 2*64*32
#define MID     128
#define OUTDIM  5120      // 32*32*5
#define BROW    125       // basis floats per row (d_out*d_in*num_freq = 5*5*5)
#define LN_EPSF 1e-5f

// ---- kernel 1 config ----
#define RPB 8             // rows per block

// ---- kernel 2 config ----
#define MT 32             // rows per CTA
#define KC 32             // k chunk
#define NT 320            // y-columns per CTA (2 "o" values * 160)
#define X2PITCH 33        // padded pitch for transposed X2 tile
#define X2SZ   (MID * X2PITCH)          // 4224 floats
#define W3BUF  (KC * NT)                // 10240 floats per buffer
#define BSOFF  (X2SZ + 2 * W3BUF)       // 24704
#define SMEM_FLOATS (BSOFF + MT * 128)  // + B tile (32 rows x 128 padded) = 28800
#define SMEM_BYTES  (SMEM_FLOATS * 4)   // 115200 B

__device__ __align__(16) float g_X2[NROWS * MID];   // intermediate X2 (2 MB scratch)

__device__ __forceinline__ void cp_async16(float* dst, const float* src) {
    unsigned u = (unsigned)__cvta_generic_to_shared(dst);
    asm volatile("cp.async.cg.shared.global [%0], [%1], 16;" :: "r"(u), "l"(src));
}
__device__ __forceinline__ void cp_commit() { asm volatile("cp.async.commit_group;"); }
template <int N> __device__ __forceinline__ void cp_wait() {
    asm volatile("cp.async.wait_group %0;" :: "n"(N));
}

// =====================================================================
// Kernel 1: stage1 (analytic LN of f*W1+b1) + stage2 (matvec + LN) -> g_X2
// One block (128 threads) handles RPB rows. Thread t owns column t.
// =====================================================================
__global__ void __launch_bounds__(128) stage12_kernel(
    const float* __restrict__ feat,
    const float* __restrict__ W1, const float* __restrict__ b1,
    const float* __restrict__ g1, const float* __restrict__ be1,
    const float* __restrict__ W2, const float* __restrict__ b2,
    const float* __restrict__ g2, const float* __restrict__ be2)
{
    __shared__ float x1s[RPB][MID];
    __shared__ float redA[5][4];
    __shared__ float redB[RPB][2][4];

    const int t = threadIdx.x;
    const int warp = t >> 5, lane = t & 31;
    const int r0 = blockIdx.x * RPB;
    const float invM = 1.0f / (float)MID;

    // ---- stage 1: LN(f*W1 + b1) is affine in scalar f -> closed form stats
    const float w = W1[t], b = b1[t];
    float s0 = w, s1 = b, s2 = w * w, s3 = w * b, s4 = b * b;
    #pragma unroll
    for (int o = 16; o; o >>= 1) {
        s0 += __shfl_down_sync(0xffffffffu, s0, o);
        s1 += __shfl_down_sync(0xffffffffu, s1, o);
        s2 += __shfl_down_sync(0xffffffffu, s2, o);
        s3 += __shfl_down_sync(0xffffffffu, s3, o);
        s4 += __shfl_down_sync(0xffffffffu, s4, o);
    }
    if (!lane) {
        redA[0][warp] = s0; redA[1][warp] = s1; redA[2][warp] = s2;
        redA[3][warp] = s3; redA[4][warp] = s4;
    }
    __syncthreads();
    const float Sw  = redA[0][0] + redA[0][1] + redA[0][2] + redA[0][3];
    const float Sb  = redA[1][0] + redA[1][1] + redA[1][2] + redA[1][3];
    const float Sww = redA[2][0] + redA[2][1] + redA[2][2] + redA[2][3];
    const float Swb = redA[3][0] + redA[3][1] + redA[3][2] + redA[3][3];
    const float Sbb = redA[4][0] + redA[4][1] + redA[4][2] + redA[4][3];

    const float gg = g1[t], bg = be1[t];
    #pragma unroll
    for (int r = 0; r < RPB; r++) {
        float f   = feat[r0 + r];
        float mu  = (f * Sw + Sb) * invM;
        float e2  = (f * f * Sww + 2.0f * f * Swb + Sbb) * invM;
        float var = e2 - mu * mu;
        float inv = rsqrtf(var + LN_EPSF);
        float v   = (f * w + b - mu) * inv * gg + bg;
        x1s[r][t] = fmaxf(v, 0.0f);
    }
    __syncthreads();

    // ---- stage 2: x2 = relu(LN(x1 @ W2 + b2))
    float acc[RPB];
    #pragma unroll
    for (int r = 0; r < RPB; r++) acc[r] = 0.0f;
    for (int k = 0; k < MID; k++) {
        float wv = W2[k * MID + t];         // coalesced; x1s[r][k] broadcast
        #pragma unroll
        for (int r = 0; r < RPB; r++) acc[r] = fmaf(x1s[r][k], wv, acc[r]);
    }
    const float bb = b2[t];
    #pragma unroll
    for (int r = 0; r < RPB; r++) acc[r] += bb;

    #pragma unroll
    for (int r = 0; r < RPB; r++) {
        float v = acc[r], s = v, q = v * v;
        #pragma unroll
        for (int o = 16; o; o >>= 1) {
            s += __shfl_down_sync(0xffffffffu, s, o);
            q += __shfl_down_sync(0xffffffffu, q, o);
        }
        if (!lane) { redB[r][0][warp] = s; redB[r][1][warp] = q; }
    }
    __syncthreads();
    const float gv = g2[t], bv = be2[t];
    #pragma unroll
    for (int r = 0; r < RPB; r++) {
        float s  = redB[r][0][0] + redB[r][0][1] + redB[r][0][2] + redB[r][0][3];
        float q  = redB[r][1][0] + redB[r][1][1] + redB[r][1][2] + redB[r][1][3];
        float mu = s * invM;
        float var = q * invM - mu * mu;
        float inv = rsqrtf(var + LN_EPSF);
        float v  = (acc[r] - mu) * inv * gv + bv;
        g_X2[(r0 + r) * MID + t] = fmaxf(v, 0.0f);
    }
}

// =====================================================================
// Kernel 2: fused GEMM (X2 @ W3 + b3) + per-row einsum with basis + write.
// CTA: 32 rows x 320 y-cols (= 2 "o" blocks). blockDim (32, 8).
// Thread (tx,ty): tx = i (0..31), ty = row group; owns acc[4 rows][2 o][5 f].
// Output staged via smem for coalesced float4 stores.
// =====================================================================
__global__ void __launch_bounds__(256) fused_gemm_einsum(
    const float* __restrict__ W3, const float* __restrict__ b3,
    const float* __restrict__ basis, float* __restrict__ out)
{
    extern __shared__ float sm[];
    float* X2_s = sm;                  // [128][33]
    float* W3_s = sm + X2SZ;           // 2 x [KC][NT]
    float* B_s  = sm + BSOFF;          // [32][128] (125 used)
    float* outs = sm + X2SZ;           // alias over W3_s after GEMM (12800 floats)

    const int tx = threadIdx.x, ty = threadIdx.y;
    const int tid = ty * 32 + tx;
    const int r0  = blockIdx.y * MT;
    const int bxo = blockIdx.x;                 // covers y cols [bxo*320, bxo*320+320)
    const float* W3b = W3 + bxo * 320;

    // load X2 tile transposed (coalesced read, padded STS)
    #pragma unroll
    for (int it = 0; it < 4; it++) {
        int idx = tid + it * 256;               // 0..1023
        int r = idx >> 5, k4 = idx & 31;
        float4 v = *reinterpret_cast<const float4*>(&g_X2[(r0 + r) * MID + k4 * 4]);
        X2_s[(k4 * 4 + 0) * X2PITCH + r] = v.x;
        X2_s[(k4 * 4 + 1) * X2PITCH + r] = v.y;
        X2_s[(k4 * 4 + 2) * X2PITCH + r] = v.z;
        X2_s[(k4 * 4 + 3) * X2PITCH + r] = v.w;
    }
    // load basis rows
    for (int i = tid; i < MT * BROW; i += 256) {
        int r = i / BROW, j = i - r * BROW;
        B_s[r * 128 + j] = basis[(size_t)(r0 + r) * BROW + j];
    }
    // prefetch W3 chunk 0
    for (int i2 = tid; i2 < (KC * NT) / 4; i2 += 256) {
        int k = i2 / 80, c4 = i2 - k * 80;
        cp_async16(W3_s + k * NT + c4 * 4, W3b + (size_t)k * OUTDIM + c4 * 4);
    }
    cp_commit();

    float acc[4][10];
    #pragma unroll
    for (int a = 0; a < 4; a++)
        #pragma unroll
        for (int j = 0; j < 10; j++) acc[a][j] = 0.0f;

    #pragma unroll 1
    for (int c = 0; c < MID / KC; c++) {
        if (c + 1 < MID / KC) {
            float* dst = W3_s + ((c + 1) & 1) * W3BUF;
            const float* src = W3b + (size_t)(c + 1) * KC * OUTDIM;
            for (int i2 = tid; i2 < (KC * NT) / 4; i2 += 256) {
                int k = i2 / 80, c4 = i2 - k * 80;
                cp_async16(dst + k * NT + c4 * 4, src + (size_t)k * OUTDIM + c4 * 4);
            }
            cp_commit();
            cp_wait<1>();
        } else {
            cp_wait<0>();
        }
        __syncthreads();

        const float* Wc = W3_s + (c & 1) * W3BUF;
        const float* Xc = X2_s + c * KC * X2PITCH;
        #pragma unroll 4
        for (int kk = 0; kk < KC; kk++) {
            float xa[4];
            #pragma unroll
            for (int rr = 0; rr < 4; rr++) xa[rr] = Xc[kk * X2PITCH + ty * 4 + rr];
            float wb[10];
            #pragma unroll
            for (int o2 = 0; o2 < 2; o2++)
                #pragma unroll
                for (int f = 0; f < 5; f++)
                    wb[o2 * 5 + f] = Wc[kk * NT + o2 * 160 + tx * 5 + f];
            #pragma unroll
            for (int rr = 0; rr < 4; rr++)
                #pragma unroll
                for (int j = 0; j < 10; j++)
                    acc[rr][j] = fmaf(xa[rr], wb[j], acc[rr][j]);
        }
        __syncthreads();
    }

    // add b3
    {
        const float* b3c = b3 + bxo * 320;
        float bb[10];
        #pragma unroll
        for (int o2 = 0; o2 < 2; o2++)
            #pragma unroll
            for (int f = 0; f < 5; f++) bb[o2 * 5 + f] = b3c[o2 * 160 + tx * 5 + f];
        #pragma unroll
        for (int rr = 0; rr < 4; rr++)
            #pragma unroll
            for (int j = 0; j < 10; j++) acc[rr][j] += bb[j];
    }

    // einsum + coalesced writeout, 4 row batches (8 rows each, one rr per warp)
    #pragma unroll 1
    for (int bt = 0; bt < 4; bt++) {
        const float* Br = B_s + (ty * 4 + bt) * 128;
        #pragma unroll
        for (int d = 0; d < 5; d++) {
            #pragma unroll
            for (int m = 0; m < 5; m++) {
                float v0 = 0.0f, v1 = 0.0f;
                #pragma unroll
                for (int f = 0; f < 5; f++) {
                    float bf = Br[d * 25 + m * 5 + f];   // broadcast LDS
                    v0 = fmaf(acc[bt][f],     bf, v0);
                    v1 = fmaf(acc[bt][5 + f], bf, v1);
                }
                outs[(ty * 10 + d)     * 160 + tx * 5 + m] = v0;  // o local 0
                outs[(ty * 10 + 5 + d) * 160 + tx * 5 + m] = v1;  // o local 1
            }
        }
        __syncthreads();
        // copy 8 rows x 10 od-rows x 160 cols = 12800 floats, float4 coalesced
        for (int i2 = tid; i2 < 3200; i2 += 256) {
            int lr  = i2 / 400;
            int rem = i2 - lr * 400;
            int od  = rem / 40, c4 = rem - od * 40;
            int gr  = r0 + lr * 4 + bt;
            *reinterpret_cast<float4*>(
                &out[(size_t)gr * (160 * 160) + (bxo * 10 + od) * 160 + c4 * 4]) =
                *reinterpret_cast<const float4*>(&outs[(lr * 10 + od) * 160 + c4 * 4]);
        }
        __syncthreads();
    }
}

extern "C" void kernel_launch(void* const* d_in, const int* in_sizes, int n_in,
                              void* d_out, int out_size)
{
    const float* feat  = (const float*)d_in[0];
    const float* basis = (const float*)d_in[1];
    const float* W1    = (const float*)d_in[2];
    const float* b1    = (const float*)d_in[3];
    const float* g1    = (const float*)d_in[4];
    const float* be1   = (const float*)d_in[5];
    const float* W2    = (const float*)d_in[6];
    const float* b2    = (const float*)d_in[7];
    const float* g2    = (const float*)d_in[8];
    const float* be2   = (const float*)d_in[9];
    const float* W3    = (const float*)d_in[10];
    const float* b3    = (const float*)d_in[11];
    float* out = (float*)d_out;

    stage12_kernel<<<NROWS / RPB, 128>>>(feat, W1, b1, g1, be1, W2, b2, g2, be2);

    cudaFuncSetAttribute(fused_gemm_einsum,
                         cudaFuncAttributeMaxDynamicSharedMemorySize, SMEM_BYTES);
    dim3 grid(OUTDIM / NT, NROWS / MT);   // (16, 128)
    dim3 blk(32, 8);
    fused_gemm_einsum<<<grid, blk, SMEM_BYTES>>>(W3, b3, basis, out);
}